// round 14
// baseline (speedup 1.0000x reference)
#include <cuda_runtime.h>
#include <cuda_fp16.h>

// ---------------- scratch (device globals; zero-init at load) ----------------
// g_tmpH layout: [x:320][c:20][my:320][t:32] as half2  (t 0..24 valid; 25..31 zero)
static __device__ uint4 g_tmpH[16384000];           // 262.1 MB
// g_imt layout: [t:25][y:320][x:320]
static __device__ float2 g_imt[2560000];            // 20.5 MB
static __device__ float2 g_tw320[320];              // e^{+2pi i j/320}
static __device__ float2 g_kT[2048000];             // kspace transposed [c:20][x:320][y:320], sign-folded
static __device__ float2 g_sT[2048000];             // conj(smaps) transposed [my:320][c:20][x:320]

// ---------------- complex helpers ----------------
__device__ __forceinline__ float2 cadd(float2 a, float2 b){ return make_float2(a.x+b.x, a.y+b.y); }
__device__ __forceinline__ float2 csub(float2 a, float2 b){ return make_float2(a.x-b.x, a.y-b.y); }
__device__ __forceinline__ float2 cmul(float2 a, float2 b){
    return make_float2(a.x*b.x - a.y*b.y, a.x*b.y + a.y*b.x);
}
__device__ __forceinline__ float2 cmuli(float2 a){ return make_float2(-a.y, a.x); }  // *(+i)

// ---------------- cp.async helpers ----------------
__device__ __forceinline__ unsigned int smem_u32(const void* p){
    return (unsigned int)__cvta_generic_to_shared(p);
}
__device__ __forceinline__ void cp_async16(unsigned int dst, const void* src){
    asm volatile("cp.async.ca.shared.global [%0], [%1], 16;" :: "r"(dst), "l"(src));
}
__device__ __forceinline__ void cp_commit(){ asm volatile("cp.async.commit_group;" ::: "memory"); }
__device__ __forceinline__ void cp_wait0(){ asm volatile("cp.async.wait_group 0;" ::: "memory"); }

// inverse 4-pt DFT: X_s = sum_r v_r e^{+2pi i rs/4}
__device__ __forceinline__ void dft4(float2 a, float2 b, float2 c, float2 d,
                                     float2& X0, float2& X1, float2& X2, float2& X3){
    float2 ac = cadd(a,c), amc = csub(a,c);
    float2 bd = cadd(b,d), bmd = csub(b,d);
    float2 ibmd = cmuli(bmd);
    X0 = cadd(ac, bd);
    X1 = cadd(amc, ibmd);
    X2 = csub(ac, bd);
    X3 = csub(amc, ibmd);
}

// inverse radix-5 butterfly: out[s] = sum_r v[r] e^{+2pi i rs/5}
__device__ __forceinline__ void bfly5(float2 v[5]){
    const float C1 =  0.309016994374947424f, S1 = 0.951056516295153572f;
    const float C2 = -0.809016994374947424f, S2 = 0.587785252292473129f;
    const float2 w1 = make_float2(C1,  S1), w2 = make_float2(C2,  S2);
    const float2 w3 = make_float2(C2, -S2), w4 = make_float2(C1, -S1);
    float2 o0 = cadd(cadd(cadd(v[1], v[2]), cadd(v[3], v[4])), v[0]);
    float2 o1 = cadd(v[0], cadd(cadd(cmul(v[1],w1), cmul(v[2],w2)), cadd(cmul(v[3],w3), cmul(v[4],w4))));
    float2 o2 = cadd(v[0], cadd(cadd(cmul(v[1],w2), cmul(v[2],w4)), cadd(cmul(v[3],w1), cmul(v[4],w3))));
    float2 o3 = cadd(v[0], cadd(cadd(cmul(v[1],w3), cmul(v[2],w1)), cadd(cmul(v[3],w4), cmul(v[4],w2))));
    float2 o4 = cadd(v[0], cadd(cadd(cmul(v[1],w4), cmul(v[2],w3)), cadd(cmul(v[3],w2), cmul(v[4],w1))));
    v[0]=o0; v[1]=o1; v[2]=o2; v[3]=o3; v[4]=o4;
}

// inverse 16-pt FFT, natural order in/out (16 = 4x4 Cooley-Tukey, e^{+i})
__device__ __forceinline__ void fft16_reg(float2 v[16]){
    const float2 W[10] = {   // e^{+2pi i k/16}, k=0..9
      { 1.f, 0.f},
      { 0.92387953251128675613f, 0.38268343236508977173f},
      { 0.70710678118654752440f, 0.70710678118654752440f},
      { 0.38268343236508977173f, 0.92387953251128675613f},
      { 0.f, 1.f},
      {-0.38268343236508977173f, 0.92387953251128675613f},
      {-0.70710678118654752440f, 0.70710678118654752440f},
      {-0.92387953251128675613f, 0.38268343236508977173f},
      {-1.f, 0.f},
      {-0.92387953251128675613f,-0.38268343236508977173f},
    };
    float2 A[16];            // A[n1*4 + m]
    #pragma unroll
    for (int n1 = 0; n1 < 4; n1++)
        dft4(v[n1], v[n1+4], v[n1+8], v[n1+12],
             A[n1*4+0], A[n1*4+1], A[n1*4+2], A[n1*4+3]);
    #pragma unroll
    for (int m = 0; m < 4; m++){
        float2 b0 = A[m];
        float2 b1 = cmul(A[4+m],  W[m]);
        float2 b2 = cmul(A[8+m],  W[2*m]);
        float2 b3 = cmul(A[12+m], W[3*m]);
        dft4(b0,b1,b2,b3, v[m], v[m+4], v[m+8], v[m+12]);   // out[m+4p]
    }
}

// inverse 20-pt DFT, natural order in/out (20 = 4x5 Cooley-Tukey, e^{+i})
__device__ __forceinline__ void dft20_reg(float2 v[20]){
    const float2 W[13] = {   // e^{+2pi i k/20}, k=0..12
      { 1.f, 0.f},
      { 0.95105651629515357212f, 0.30901699437494742410f},
      { 0.80901699437494742410f, 0.58778525229247312917f},
      { 0.58778525229247312917f, 0.80901699437494742410f},
      { 0.30901699437494742410f, 0.95105651629515357212f},
      { 0.f, 1.f},
      {-0.30901699437494742410f, 0.95105651629515357212f},
      {-0.58778525229247312917f, 0.80901699437494742410f},
      {-0.80901699437494742410f, 0.58778525229247312917f},
      {-0.95105651629515357212f, 0.30901699437494742410f},
      {-1.f, 0.f},
      {-0.95105651629515357212f,-0.30901699437494742410f},
      {-0.80901699437494742410f,-0.58778525229247312917f},
    };
    float2 A[20];            // A[a*5 + m]
    #pragma unroll
    for (int a = 0; a < 4; a++){
        float2 t[5];
        #pragma unroll
        for (int b = 0; b < 5; b++) t[b] = v[a + 4*b];
        bfly5(t);
        #pragma unroll
        for (int m = 0; m < 5; m++) A[a*5+m] = t[m];
    }
    #pragma unroll
    for (int m = 0; m < 5; m++){
        float2 b0 = A[m];
        float2 b1 = cmul(A[5+m],  W[m]);
        float2 b2 = cmul(A[10+m], W[2*m]);
        float2 b3 = cmul(A[15+m], W[3*m]);
        dft4(b0,b1,b2,b3, v[m], v[m+5], v[m+10], v[m+15]);  // out[m+5q]
    }
}

__global__ void twinit_kernel(){
    int j = threadIdx.x;
    float ang = 6.28318530717958647692f * (float)j / 320.f;
    float sn, cs; sincosf(ang, &sn, &cs);
    g_tw320[j] = make_float2(cs, sn);   // e^{+i ang}
}

// ------------- prep: transpose kspace (sign-folded) and conj(smaps) ---------------------------
__global__ void __launch_bounds__(256) prep_kernel(
    const float* __restrict__ kre, const float* __restrict__ kim,
    const float* __restrict__ sre, const float* __restrict__ sim){
    int p = blockIdx.x*256 + threadIdx.x;             // 0..102399
    {
        int x = p / 320, y = p - x*320;
        float sg = ((x + y) & 1) ? -1.f : 1.f;
        #pragma unroll 4
        for (int c = 0; c < 20; c++){
            g_kT[c*102400 + p] = make_float2(kre[p*20 + c]*sg, kim[p*20 + c]*sg);
        }
    }
    {
        int my = p / 320, x = p - my*320;
        int src = (x*320 + my)*20;
        #pragma unroll 4
        for (int c = 0; c < 20; c++){
            g_sT[(my*20 + c)*320 + x] = make_float2(sre[src + c], -sim[src + c]);  // conj folded
        }
    }
}

// ------------- Stage A: mask*kT, iFFT along y (four-step 20x16); block = (x, c, t-half) -------
// dynamic smem: sIn fp32[16*321] (41088) | sMid half2[16*336] (21504) | tw[320] (2560) = 65152 B
__global__ void __launch_bounds__(320, 3) stageA_kernel(const float* __restrict__ mask){
    extern __shared__ char dynA[];
    float2*       sIn   = (float2*)dynA;                   // [f][y] stride 321 (also reused as half2 out)
    __half2*      sMid  = (__half2*)(dynA + 41088);        // [f*336 + m2*21 + n1]
    float2*       tw    = (float2*)(dynA + 41088 + 21504); // 320
    unsigned int* sOutW = (unsigned int*)dynA;             // phase-2 output, half2 raw, [f*321 + my]
    const int x = blockIdx.x, c = blockIdx.y, half = blockIdx.z;
    const int tid = threadIdx.x;        // = y
    tw[tid] = g_tw320[tid];

    const float2 kv = g_kT[c*102400 + x*320 + tid];
    const float* mrow = mask + (x*320 + tid)*500 + c*25 + half*16;
    const int nv = half ? 9 : 16;       // valid frames in this half
    #pragma unroll
    for (int f = 0; f < 16; f++){
        float m = (f < nv) ? mrow[f] : 0.f;
        sIn[f*321 + tid] = make_float2(kv.x*m, kv.y*m);
    }
    __syncthreads();

    // phase 1: (f, n1), n1 in 0..19 — 320 tasks; 16-pt FFT over n2 (stride 20)
    {
        const int f = tid / 20, n1 = tid - (tid/20)*20;
        const float2* base = sIn + f*321;
        float2 v[16];
        #pragma unroll
        for (int n2 = 0; n2 < 16; n2++) v[n2] = base[n1 + 20*n2];
        fft16_reg(v);
        __half2* mb = sMid + f*336 + n1;
        int idx = 0;                                  // n1*m2 mod 320
        #pragma unroll
        for (int m2 = 0; m2 < 16; m2++){
            float2 r = cmul(v[m2], tw[idx]);
            mb[m2*21] = __floats2half2_rn(r.x, r.y);
            idx += n1; if (idx >= 320) idx -= 320;
        }
    }
    __syncthreads();

    // phase 2: (f, m2) — 256 tasks; 20-pt DFT over n1; out[p] = X[m2+16p] written half2 over sIn
    if (tid < 256){
        const int f = tid >> 4, m2 = tid & 15;
        const __half2* mb = sMid + f*336 + m2*21;
        float2 v[20];
        #pragma unroll
        for (int n1 = 0; n1 < 20; n1++) v[n1] = __half22float2(mb[n1]);
        dft20_reg(v);
        unsigned int* ob = sOutW + f*321 + m2;
        #pragma unroll
        for (int p = 0; p < 20; p++){
            __half2 h = __floats2half2_rn(v[p].x, v[p].y);
            ob[16*p] = *reinterpret_cast<unsigned int*>(&h);   // my = m2 + 16p
        }
    }
    __syncthreads();

    // store: thread = my, 16 frames -> 64B contiguous fp16
    uint4* dst = g_tmpH + ((size_t)(x*20 + c)*320 + tid)*8 + half*4;
    #pragma unroll
    for (int i = 0; i < 4; i++){
        dst[i] = make_uint4(sOutW[(4*i+0)*321 + tid], sOutW[(4*i+1)*321 + tid],
                            sOutW[(4*i+2)*321 + tid], sOutW[(4*i+3)*321 + tid]);
    }
}

// ------------- Stage B: iFFT along x (four-step 16x20) + coil combine; block = (my, t-half) ---
// dynamic smem: sIn half2[320*20] (25600) | sMid fp32[16*340] (43520) | tw[320] (2560) = 71680 B
__global__ void __launch_bounds__(320, 3) stageB_kernel(){
    extern __shared__ char dynB[];
    __half2* sIn  = (__half2*)dynB;                    // [x*20 + f]
    float2*  sMid = (float2*)(dynB + 25600);           // [f*340 + m*17 + n1]
    float2*  tw   = (float2*)(dynB + 25600 + 43520);   // 320
    const int my = blockIdx.x, half = blockIdx.y;
    const int tid = threadIdx.x;        // = x for staging
    tw[tid] = g_tw320[tid];
    const int f1 = tid >> 4, n1 = tid & 15;      // phase-1 ids (tid < 256)
    const int f2 = tid / 20, m2 = tid - (tid/20)*20;   // phase-2 ids

    float2 acc[16];
    #pragma unroll
    for (int i = 0; i < 16; i++) acc[i] = make_float2(0.f,0.f);

    // zero-register staging: cp.async 64B per thread per coil
    const unsigned int sInW = smem_u32(sIn) + tid*80;
    // coil stride at fixed (x,my): 320(my) * 8 uint4 = 2560 uint4 = 40960 bytes  (R13 bug: was 5120)
    const char* gsrc = (const char*)(g_tmpH + ((size_t)(tid*20)*320 + my)*8 + half*4);
    #pragma unroll
    for (int i = 0; i < 4; i++) cp_async16(sInW + 16*i, gsrc + 16*i);
    cp_commit();

    const float2* Srow = g_sT + (size_t)my*6400;   // [c*320 + x]

    for (int c = 0; c < 20; c++){
        cp_wait0();
        __syncthreads();                 // sIn(c) visible to all; phase2(c-1) done with sMid

        // phase 1: (f, n1) — 256 tasks; 20-pt DFT over n2 (x = n1 + 16*n2)
        if (tid < 256){
            float2 v[20];
            #pragma unroll
            for (int n2 = 0; n2 < 20; n2++)
                v[n2] = __half22float2(sIn[(n1 + 16*n2)*20 + f1]);
            dft20_reg(v);
            float2* mb = sMid + f1*340 + n1;
            int idx = 0;                              // n1*m mod 320
            #pragma unroll
            for (int m = 0; m < 20; m++){
                mb[m*17] = cmul(v[m], tw[idx]);
                idx += n1; if (idx >= 320) idx -= 320;
            }
        }
        __syncthreads();                 // phase1 done: sIn free, sMid ready

        if (c < 19){                     // stage next coil under phase 2 (async, no regs)
            gsrc += 40960;               // one coil = 320(my) * 8 uint4 = 40960 B
            #pragma unroll
            for (int i = 0; i < 4; i++) cp_async16(sInW + 16*i, gsrc + 16*i);
            cp_commit();
        }

        // phase 2: (f, m) — 320 tasks; 16-pt FFT over n1; out[p] = X[m+20p]; accumulate
        {
            const float2* mb = sMid + f2*340 + m2*17;
            float2 v[16];
            #pragma unroll
            for (int k = 0; k < 16; k++) v[k] = mb[k];
            fft16_reg(v);
            const float2* Sc = Srow + c*320 + m2;
            #pragma unroll
            for (int p = 0; p < 16; p++)
                acc[p] = cadd(acc[p], cmul(v[p], Sc[20*p]));   // conj(smaps), LDG (L2-resident)
        }
    }

    // store directly: thread (f2,m2) owns frame t=half*16+f2, x = m2+20p (160B runs per lane-group)
    const int nv = half ? 9 : 16;
    if (f2 < nv){
        const float sc = ((m2 + my) & 1) ? -(1.f/320.f) : (1.f/320.f);  // (-1)^(x+my), 20p even
        const int t = half*16 + f2;
        float2* ob = g_imt + (size_t)t*102400 + my*320 + m2;
        #pragma unroll
        for (int p = 0; p < 16; p++)
            ob[20*p] = make_float2(acc[p].x*sc, acc[p].y*sc);
    }
}

// ------------- Stage C: 25-frame bilinear warp + sum ------------------------------------------
__global__ void __launch_bounds__(256) stageC_kernel(
    const float* __restrict__ flow, float* __restrict__ out){
    int p = blockIdx.x*256 + threadIdx.x;             // 0..102399
    int x = p % 320;                                  // x fastest -> coalesced gathers
    int y = p / 320;
    const float* fl = flow + (x*320 + y)*50;          // [x][y][2][25]
    float2 acc = make_float2(0.f, 0.f);
    for (int t = 0; t < 25; t++){
        float u = fl[t], v = fl[25 + t];
        float xs = fminf(fmaxf((float)x + u, 0.f), 319.f);
        float ys = fminf(fmaxf((float)y + v, 0.f), 319.f);
        int x0 = (int)floorf(xs), y0 = (int)floorf(ys);
        int x1 = min(x0 + 1, 319), y1 = min(y0 + 1, 319);
        float wx = xs - (float)x0, wy = ys - (float)y0;
        const float2* im = g_imt + (size_t)t*102400;  // [y][x]
        float2 v00 = im[y0*320 + x0];
        float2 v10 = im[y0*320 + x1];
        float2 v01 = im[y1*320 + x0];
        float2 v11 = im[y1*320 + x1];
        float w00 = (1.f-wx)*(1.f-wy), w10 = wx*(1.f-wy);
        float w01 = (1.f-wx)*wy,       w11 = wx*wy;
        acc.x += v00.x*w00 + v10.x*w10 + v01.x*w01 + v11.x*w11;
        acc.y += v00.y*w00 + v10.y*w10 + v01.y*w01 + v11.y*w11;
    }
    out[x*320 + y]          = acc.x;                  // [2,Nx,Ny]: real plane
    out[102400 + x*320 + y] = acc.y;                  // imag plane
}

extern "C" void kernel_launch(void* const* d_in, const int* in_sizes, int n_in,
                              void* d_out, int out_size) {
    const float* kre  = (const float*)d_in[0];
    const float* kim  = (const float*)d_in[1];
    const float* mask = (const float*)d_in[2];
    const float* sre  = (const float*)d_in[3];
    const float* sim  = (const float*)d_in[4];
    const float* flow = (const float*)d_in[5];
    float* out = (float*)d_out;

    const int smemA = 41088 + 21504 + 2560;           // 65152
    const int smemB = 25600 + 43520 + 2560;           // 71680
    cudaFuncSetAttribute(stageA_kernel, cudaFuncAttributeMaxDynamicSharedMemorySize, smemA);
    cudaFuncSetAttribute(stageB_kernel, cudaFuncAttributeMaxDynamicSharedMemorySize, smemB);

    twinit_kernel<<<1, 320>>>();
    prep_kernel<<<400, 256>>>(kre, kim, sre, sim);
    stageA_kernel<<<dim3(320, 20, 2), 320, smemA>>>(mask);
    stageB_kernel<<<dim3(320, 2), 320, smemB>>>();
    stageC_kernel<<<400, 256>>>(flow, out);
}